// round 14
// baseline (speedup 1.0000x reference)
#include <cuda_runtime.h>
#include <cuda_bf16.h>
#include <cstdint>

// ---------------- problem constants ----------------
#define AA 64
#define MSEQ 128
#define DD 128
#define MMI 127

#define NPAIR_TRI 2080
#define NP (2*NPAIR_TRI + AA*AA)          // 8256 pairs
#define NBLK (NP/2)                        // 4128 CTAs, 2 pairs each

// ---------------- device scratch (no allocs) ----------------
// bf16 hi/lo increment tiles: [tsr(2)][seq(64)][row(128)][col(128)]
__device__ __align__(16) __nv_bfloat16 g_hi[2*64*128*128];   // 4 MB
__device__ __align__(16) __nv_bfloat16 g_lo[2*64*128*128];   // 4 MB
__device__ float g_partials[NP];

// ---------------- smem byte map ----------------
// GEMM: cp.async double-buffered K-chunks of 16.
// Per set: A_hi, A_lo, B_hi, B_lo buffers of 128 rows x 48B
// (32B data + 16B pad; bank stride 12 -> ldsm rows hit distinct banks).
#define KC 16
#define ROWB 48
#define BUFB 6144                          // 128*48
#define SETB 24576                         // 4 buffers
// sM disjoint from GEMM buffers (PDE overlaps next pair's GEMM)
#define SM_OFF 49152                       // after 2 sets
#define SM_STRIDE 130
#define SMEM_BYTES (SM_OFF + 66560)        // 115712; x2 = 226KB <= 228KB/SM

#define BAR_GEMM() asm volatile("bar.sync 1, 256;" ::: "memory")
#define BAR_HAND() asm volatile("bar.sync 2, 288;" ::: "memory")   // epilogue -> PDE
#define BAR_PDED() asm volatile("bar.sync 3, 288;" ::: "memory")   // PDE done -> epi overwrite

__device__ __forceinline__ uint32_t smem_u32(const void* p) {
    uint32_t a;
    asm("{ .reg .u64 t; cvta.to.shared.u64 t, %1; cvt.u32.u64 %0, t; }" : "=r"(a) : "l"(p));
    return a;
}

__device__ __forceinline__ void ldsm4(uint32_t* r, uint32_t addr) {
    asm volatile("ldmatrix.sync.aligned.m8n8.x4.shared.b16 {%0,%1,%2,%3}, [%4];"
        : "=r"(r[0]), "=r"(r[1]), "=r"(r[2]), "=r"(r[3]) : "r"(addr));
}

__device__ __forceinline__ void mma16816(float* c, const uint32_t* a,
                                         uint32_t b0, uint32_t b1) {
    asm volatile(
        "mma.sync.aligned.m16n8k16.row.col.f32.bf16.bf16.f32 "
        "{%0,%1,%2,%3}, {%4,%5,%6,%7}, {%8,%9}, {%0,%1,%2,%3};"
        : "+f"(c[0]), "+f"(c[1]), "+f"(c[2]), "+f"(c[3])
        : "r"(a[0]), "r"(a[1]), "r"(a[2]), "r"(a[3]), "r"(b0), "r"(b1));
}

__device__ __forceinline__ void decode_pair(int pid, int& g, int& a, int& b, float& w) {
    if (pid < 2 * NPAIR_TRI) {
        g = (pid < NPAIR_TRI) ? 0 : 1;
        int t = pid - g * NPAIR_TRI;
        int aa = 0;
        while (t >= (AA - aa)) { t -= (AA - aa); ++aa; }
        a = aa; b = aa + t;
        w = (a == b) ? 1.0f : 2.0f;
    } else {
        g = 2;
        int t = pid - 2 * NPAIR_TRI;
        a = t >> 6; b = t & 63;
        w = -2.0f;
    }
}

// ---------------- precompute: bf16 hi/lo increments ----------------
__global__ __launch_bounds__(256)
void sig_precompute_kernel(const float* __restrict__ X, const float* __restrict__ Y) {
    const int blk = blockIdx.x;                 // tsr*64 + seq
    const int seq = blk & 63;
    const int tsr = blk >> 6;
    const float* src = (tsr ? Y : X) + (size_t)seq * MSEQ * DD;
    __nv_bfloat16* hi = g_hi + (size_t)blk * 128 * 128;
    __nv_bfloat16* lo = g_lo + (size_t)blk * 128 * 128;

    const int tid = threadIdx.x;
#pragma unroll
    for (int i = 0; i < 16; ++i) {
        int idx = tid + i * 256;                // 0..4095 float4 groups
        int r  = idx >> 5;
        int c4 = (idx & 31) << 2;
        float4 cur = *reinterpret_cast<const float4*>(src + r * DD + c4);
        float4 nxt = (r < MMI) ? *reinterpret_cast<const float4*>(src + (r + 1) * DD + c4) : cur;
        float i0 = nxt.x - cur.x, i1 = nxt.y - cur.y, i2 = nxt.z - cur.z, i3 = nxt.w - cur.w;
        __nv_bfloat16 h0 = __float2bfloat16(i0), h1 = __float2bfloat16(i1);
        __nv_bfloat16 h2 = __float2bfloat16(i2), h3 = __float2bfloat16(i3);
        __nv_bfloat16 l0 = __float2bfloat16(i0 - __bfloat162float(h0));
        __nv_bfloat16 l1 = __float2bfloat16(i1 - __bfloat162float(h1));
        __nv_bfloat16 l2 = __float2bfloat16(i2 - __bfloat162float(h2));
        __nv_bfloat16 l3 = __float2bfloat16(i3 - __bfloat162float(h3));
        __nv_bfloat162 hp0(h0, h1), hp1(h2, h3), lp0(l0, l1), lp1(l2, l3);
        uint2 hv, lv;
        hv.x = *reinterpret_cast<uint32_t*>(&hp0); hv.y = *reinterpret_cast<uint32_t*>(&hp1);
        lv.x = *reinterpret_cast<uint32_t*>(&lp0); lv.y = *reinterpret_cast<uint32_t*>(&lp1);
        *reinterpret_cast<uint2*>(hi + r * 128 + c4) = hv;
        *reinterpret_cast<uint2*>(lo + r * 128 + c4) = lv;
    }
}

// ---------------- fused kernel: 2 pairs/CTA, warp-specialized PDE ----------------
__global__ __launch_bounds__(288, 2)
void sig_block_kernel() {
    extern __shared__ unsigned char smem[];
    const uint32_t sbase = smem_u32(smem);
    const int tid = threadIdx.x;
    const int wid = tid >> 5, lane = tid & 31;
    float* sM = reinterpret_cast<float*>(smem + SM_OFF);

    // ================== PDE warp (warp 8) ==================
    if (wid == 8) {
#pragma unroll 1
        for (int it = 0; it < 2; ++it) {
            BAR_HAND();                         // wait for epilogue(it)
            // ---- single-warp register wavefront over sM = (M-1) ----
            const float* mp = sM + 516 * lane - 2;   // mp[129*i + s]
            const int p1 = 4 * lane + 1, p2 = p1 + 1, p3 = p1 + 2, p4 = p1 + 3;
            float cur0 = 1.f, cur1 = 1.f, cur2 = 1.f, cur3 = 1.f;
            float pr0 = 1.f, pr1 = 1.f, pr2 = 1.f;
            float shc_prev = 1.f;
#pragma unroll 2
            for (int s = 2; s <= 127; ++s) {     // guarded phase
                float shc = __shfl_up_sync(0xffffffffu, cur3, 1);
                if (lane == 0) shc = 1.f;
                const float shp = shc_prev;
                const float m0 = mp[s];
                const float m1 = mp[129 + s];
                const float m2 = mp[258 + s];
                const float m3 = mp[387 + s];
                const float v0 = cur0 + shc  + shp * m0;
                const float v1 = cur1 + cur0 + pr0 * m1;
                const float v2 = cur2 + cur1 + pr1 * m2;
                const float v3 = cur3 + cur2 + pr2 * m3;
                shc_prev = shc;
                if (s > p1) { pr0 = cur0; cur0 = v0; }
                if (s > p2) { pr1 = cur1; cur1 = v1; }
                if (s > p3) { pr2 = cur2; cur2 = v2; }
                if (s > p4) { cur3 = v3; }
            }
#pragma unroll 2
            for (int s = 128; s <= 254; ++s) {   // unguarded phase
                float shc = __shfl_up_sync(0xffffffffu, cur3, 1);
                if (lane == 0) shc = 1.f;
                const float shp = shc_prev;
                const float m0 = mp[s];
                const float m1 = mp[129 + s];
                const float m2 = mp[258 + s];
                const float m3 = mp[387 + s];
                const float v0 = cur0 + shc  + shp * m0;
                const float v1 = cur1 + cur0 + pr0 * m1;
                const float v2 = cur2 + cur1 + pr1 * m2;
                const float v3 = cur3 + cur2 + pr2 * m3;
                shc_prev = shc;
                pr0 = cur0; cur0 = v0;
                pr1 = cur1; cur1 = v1;
                pr2 = cur2; cur2 = v2;
                cur3 = v3;
            }
            if (lane == 31) {
                int pid = 2 * blockIdx.x + it;
                int g, a, b; float w;
                decode_pair(pid, g, a, b, w);
                g_partials[pid] = w * cur2;      // K[127][127]
            }
            if (it == 0) BAR_PDED();             // release sM for epilogue(1)
        }
        return;
    }

    // ================== GEMM warps (0-7) ==================
    const int mw = wid >> 1, nw = wid & 1;       // m32 x n64 warp tile
    const int ablk = lane >> 3;
    const int arow = ((ablk & 1) << 3) + (lane & 7);
    const uint32_t aoff = (uint32_t)((32 * mw + arow) * ROWB + ((ablk >> 1) << 4));
    const int bblk = lane >> 3;
    const uint32_t boff = (uint32_t)((64 * nw + ((bblk >> 1) << 3) + (lane & 7)) * ROWB
                                     + ((bblk & 1) << 4));

#pragma unroll 1
    for (int it = 0; it < 2; ++it) {
        const int pid = 2 * blockIdx.x + it;
        int g, a, b; float w;
        decode_pair(pid, g, a, b, w);
        const int idxA = ((g == 1) ? 64 : 0) + a;     // Y for YY else X
        const int idxB = ((g == 0) ? 0 : 64) + b;     // X for XX else Y
        const __nv_bfloat16* gAh = g_hi + (size_t)idxA * 16384;
        const __nv_bfloat16* gAl = g_lo + (size_t)idxA * 16384;
        const __nv_bfloat16* gBh = g_hi + (size_t)idxB * 16384;
        const __nv_bfloat16* gBl = g_lo + (size_t)idxB * 16384;

        float acc[64];
#pragma unroll
        for (int i = 0; i < 64; ++i) acc[i] = 0.0f;

        // chunk loader: 1024 x 16B per chunk over 256 threads
        auto issue_chunk = [&](int c, uint32_t setbase) {
#pragma unroll
            for (int j = 0; j < 4; ++j) {
                int idx = tid + j * 256;             // 0..1023
                int buf = idx >> 8;                  // 0..3
                int r   = (idx >> 1) & 127;
                int cc  = idx & 1;                   // 16B col
                uint32_t dst = sbase + setbase + buf * BUFB + (uint32_t)(r * ROWB + cc * 16);
                const __nv_bfloat16* gp = (buf == 0) ? gAh : (buf == 1) ? gAl
                                        : (buf == 2) ? gBh : gBl;
                const void* src = gp + r * 128 + c * KC + cc * 8;
                asm volatile("cp.async.cg.shared.global [%0], [%1], 16;"
                    :: "r"(dst), "l"(src));
            }
            asm volatile("cp.async.commit_group;");
        };

        issue_chunk(0, 0);
        issue_chunk(1, SETB);
#pragma unroll
        for (int c = 0; c < 8; ++c) {
            if (c < 7) asm volatile("cp.async.wait_group 1;");
            else       asm volatile("cp.async.wait_group 0;");
            BAR_GEMM();                              // chunk c visible
            const uint32_t setbase = (c & 1) ? SETB : 0;
            // ---- compute chunk: k=16, term-major mma (RAW distance 4) ----
            uint32_t ah0[4], al0[4], ah1[4], al1[4];
            const uint32_t ab = sbase + setbase + aoff;
            ldsm4(ah0, ab);
            ldsm4(ah1, ab + 16 * ROWB);
            ldsm4(al0, ab + BUFB);
            ldsm4(al1, ab + BUFB + 16 * ROWB);
#pragma unroll
            for (int j2 = 0; j2 < 4; ++j2) {
                uint32_t bh[4], bl[4];
                const uint32_t bb = sbase + setbase + 2 * BUFB + boff + j2 * (16 * ROWB);
                ldsm4(bh, bb);
                ldsm4(bl, bb + BUFB);
                float* c00 = acc + (2 * j2) * 4;
                float* c01 = acc + (2 * j2 + 1) * 4;
                float* c10 = acc + 32 + (2 * j2) * 4;
                float* c11 = acc + 32 + (2 * j2 + 1) * 4;
                // term-major: hh x4, hl x4, lh x4
                mma16816(c00, ah0, bh[0], bh[1]);
                mma16816(c01, ah0, bh[2], bh[3]);
                mma16816(c10, ah1, bh[0], bh[1]);
                mma16816(c11, ah1, bh[2], bh[3]);
                mma16816(c00, ah0, bl[0], bl[1]);
                mma16816(c01, ah0, bl[2], bl[3]);
                mma16816(c10, ah1, bl[0], bl[1]);
                mma16816(c11, ah1, bl[2], bl[3]);
                mma16816(c00, al0, bh[0], bh[1]);
                mma16816(c01, al0, bh[2], bh[3]);
                mma16816(c10, al1, bh[0], bh[1]);
                mma16816(c11, al1, bh[2], bh[3]);
            }
            BAR_GEMM();                              // all reads of this set done
            if (c < 6) issue_chunk(c + 2, setbase);
        }

        if (it == 1) BAR_PDED();                     // PDE(0) done -> sM free

        // ---- epilogue: acc-1 -> sM (fp32, stride 130) ----
        {
            const int rr = lane >> 2;
            const int cb = (lane & 3) << 1;
#pragma unroll
            for (int mt = 0; mt < 2; ++mt) {
                const int r0 = 32 * mw + 16 * mt + rr;
#pragma unroll
                for (int n8 = 0; n8 < 8; ++n8) {
                    const int col = 64 * nw + 8 * n8 + cb;
                    float* c = acc + mt * 32 + n8 * 4;
                    *reinterpret_cast<float2*>(&sM[r0 * SM_STRIDE + col])
                        = make_float2(c[0] - 1.0f, c[1] - 1.0f);
                    *reinterpret_cast<float2*>(&sM[(r0 + 8) * SM_STRIDE + col])
                        = make_float2(c[2] - 1.0f, c[3] - 1.0f);
                }
            }
        }
        BAR_HAND();                                  // epilogue(it) -> PDE warp go
    }
}

// ---------------- deterministic FP64 reduction ----------------
__global__ void sig_reduce_kernel(float* __restrict__ out) {
    __shared__ double sh[256];
    const int tid = threadIdx.x;
    double acc = 0.0;
    for (int i = tid; i < NP; i += 256) acc += (double)g_partials[i];
    sh[tid] = acc;
    __syncthreads();
    for (int s = 128; s > 0; s >>= 1) {
        if (tid < s) sh[tid] += sh[tid + s];
        __syncthreads();
    }
    if (tid == 0) out[0] = (float)(sh[0] * (1.0 / 4096.0));
}

extern "C" void kernel_launch(void* const* d_in, const int* in_sizes, int n_in,
                              void* d_out, int out_size) {
    const float* X = (const float*)d_in[0];
    const float* Y = (const float*)d_in[1];
    float* out = (float*)d_out;

    cudaFuncSetAttribute(sig_block_kernel,
                         cudaFuncAttributeMaxDynamicSharedMemorySize, SMEM_BYTES);

    sig_precompute_kernel<<<128, 256>>>(X, Y);
    sig_block_kernel<<<NBLK, 288, SMEM_BYTES>>>();
    sig_reduce_kernel<<<1, 256>>>(out);
}

// round 16
// speedup vs baseline: 1.2169x; 1.2169x over previous
#include <cuda_runtime.h>
#include <cuda_bf16.h>
#include <cstdint>

// ---------------- problem constants ----------------
#define AA 64
#define MSEQ 128
#define DD 128
#define MMI 127

#define NPAIR_TRI 2080
#define NP (2*NPAIR_TRI + AA*AA)          // 8256 pair-blocks

// ---------------- device scratch (no allocs) ----------------
// bf16 hi/lo increment tiles: [tsr(2)][seq(64)][row(128)][col(128)]
__device__ __align__(16) __nv_bfloat16 g_hi[2*64*128*128];   // 4 MB
__device__ __align__(16) __nv_bfloat16 g_lo[2*64*128*128];   // 4 MB
__device__ float g_partials[NP];

// ---------------- smem byte map (block kernel) ----------------
// GEMM phase: cp.async double-buffered K-chunks of 32.
// Per chunk-set: A_hi, A_lo, B_hi, B_lo buffers of 128 rows x 80B
// (64B data + 16B pad; ldsm row banks {0,20,8,28,16,4,24,12}*4: conflict-free).
#define KC 32
#define ROWB 80
#define BUFB 10240                        // 128*80
#define SETB 40960                        // 4 buffers per set
#define SMEM_BYTES 81920                  // 2 sets; occ 2 (163KB/SM)
// PDE phase aliases buffers: sM = (M-1), fp32, 128 x SM_STRIDE (66560 B)
#define SM_STRIDE 130

__device__ __forceinline__ uint32_t smem_u32(const void* p) {
    uint32_t a;
    asm("{ .reg .u64 t; cvta.to.shared.u64 t, %1; cvt.u32.u64 %0, t; }" : "=r"(a) : "l"(p));
    return a;
}

__device__ __forceinline__ void ldsm4(uint32_t* r, uint32_t addr) {
    asm volatile("ldmatrix.sync.aligned.m8n8.x4.shared.b16 {%0,%1,%2,%3}, [%4];"
        : "=r"(r[0]), "=r"(r[1]), "=r"(r[2]), "=r"(r[3]) : "r"(addr));
}

__device__ __forceinline__ void mma16816(float* c, const uint32_t* a,
                                         uint32_t b0, uint32_t b1) {
    asm volatile(
        "mma.sync.aligned.m16n8k16.row.col.f32.bf16.bf16.f32 "
        "{%0,%1,%2,%3}, {%4,%5,%6,%7}, {%8,%9}, {%0,%1,%2,%3};"
        : "+f"(c[0]), "+f"(c[1]), "+f"(c[2]), "+f"(c[3])
        : "r"(a[0]), "r"(a[1]), "r"(a[2]), "r"(a[3]), "r"(b0), "r"(b1));
}

// ---------------- precompute: bf16 hi/lo increments ----------------
__global__ __launch_bounds__(256)
void sig_precompute_kernel(const float* __restrict__ X, const float* __restrict__ Y) {
    const int blk = blockIdx.x;                 // tsr*64 + seq
    const int seq = blk & 63;
    const int tsr = blk >> 6;
    const float* src = (tsr ? Y : X) + (size_t)seq * MSEQ * DD;
    __nv_bfloat16* hi = g_hi + (size_t)blk * 128 * 128;
    __nv_bfloat16* lo = g_lo + (size_t)blk * 128 * 128;

    const int tid = threadIdx.x;
#pragma unroll
    for (int i = 0; i < 16; ++i) {
        int idx = tid + i * 256;                // 0..4095 float4 groups
        int r  = idx >> 5;
        int c4 = (idx & 31) << 2;
        float4 cur = *reinterpret_cast<const float4*>(src + r * DD + c4);
        float4 nxt = (r < MMI) ? *reinterpret_cast<const float4*>(src + (r + 1) * DD + c4) : cur;
        float i0 = nxt.x - cur.x, i1 = nxt.y - cur.y, i2 = nxt.z - cur.z, i3 = nxt.w - cur.w;
        __nv_bfloat16 h0 = __float2bfloat16(i0), h1 = __float2bfloat16(i1);
        __nv_bfloat16 h2 = __float2bfloat16(i2), h3 = __float2bfloat16(i3);
        __nv_bfloat16 l0 = __float2bfloat16(i0 - __bfloat162float(h0));
        __nv_bfloat16 l1 = __float2bfloat16(i1 - __bfloat162float(h1));
        __nv_bfloat16 l2 = __float2bfloat16(i2 - __bfloat162float(h2));
        __nv_bfloat16 l3 = __float2bfloat16(i3 - __bfloat162float(h3));
        __nv_bfloat162 hp0(h0, h1), hp1(h2, h3), lp0(l0, l1), lp1(l2, l3);
        uint2 hv, lv;
        hv.x = *reinterpret_cast<uint32_t*>(&hp0); hv.y = *reinterpret_cast<uint32_t*>(&hp1);
        lv.x = *reinterpret_cast<uint32_t*>(&lp0); lv.y = *reinterpret_cast<uint32_t*>(&lp1);
        *reinterpret_cast<uint2*>(hi + r * 128 + c4) = hv;
        *reinterpret_cast<uint2*>(lo + r * 128 + c4) = lv;
    }
}

// ---------------- fused per-pair kernel ----------------
__global__ __launch_bounds__(256, 2)
void sig_block_kernel() {
    extern __shared__ unsigned char smem[];
    const uint32_t sbase = smem_u32(smem);
    const int bid = blockIdx.x;
    const int tid = threadIdx.x;
    const int wid = tid >> 5, lane = tid & 31;

    // ---- decode (gram type, pair) ----
    int g, a, b;
    float w;
    if (bid < 2 * NPAIR_TRI) {
        g = (bid < NPAIR_TRI) ? 0 : 1;
        int t = bid - g * NPAIR_TRI;
        int aa = 0;
        while (t >= (AA - aa)) { t -= (AA - aa); ++aa; }
        a = aa; b = aa + t;
        w = (a == b) ? 1.0f : 2.0f;
    } else {
        g = 2;
        int t = bid - 2 * NPAIR_TRI;
        a = t >> 6; b = t & 63;
        w = -2.0f;
    }
    const int idxA = ((g == 1) ? 64 : 0) + a;     // Y for YY else X
    const int idxB = ((g == 0) ? 0 : 64) + b;     // X for XX else Y
    const __nv_bfloat16* gAh = g_hi + (size_t)idxA * 16384;
    const __nv_bfloat16* gAl = g_lo + (size_t)idxA * 16384;
    const __nv_bfloat16* gBh = g_hi + (size_t)idxB * 16384;
    const __nv_bfloat16* gBl = g_lo + (size_t)idxB * 16384;

    // ---- warp tile: m32 x n64 (4 x 2 warp grid) ----
    const int mw = wid >> 1, nw = wid & 1;
    // A ldsm x4 blocks: 0:(m0-7,k0) 1:(m8-15,k0) 2:(m0-7,k8) 3:(m8-15,k8)
    const int ablk = lane >> 3;
    const int arow = ((ablk & 1) << 3) + (lane & 7);
    const uint32_t aoff = (uint32_t)((32 * mw + arow) * ROWB + ((ablk >> 1) << 4));
    // B ldsm x4 blocks: 0:(n0-7,k0) 1:(n0-7,k8) 2:(n8-15,k0) 3:(n8-15,k8)
    const int bblk = lane >> 3;
    const uint32_t boff = (uint32_t)((64 * nw + ((bblk >> 1) << 3) + (lane & 7)) * ROWB
                                     + ((bblk & 1) << 4));

    float acc[64];
#pragma unroll
    for (int i = 0; i < 64; ++i) acc[i] = 0.0f;

    // ---- cp.async chunk loader: 8 x 16B per thread per chunk ----
    auto issue_chunk = [&](int c, uint32_t setbase) {
#pragma unroll
        for (int j = 0; j < 8; ++j) {
            int idx = tid + j * 256;            // 0..2047
            int buf = idx >> 9;                 // 0..3
            int r   = (idx >> 2) & 127;
            int cc  = idx & 3;                  // 16B column within 64B row data
            uint32_t dst = sbase + setbase + buf * BUFB + (uint32_t)(r * ROWB + cc * 16);
            const __nv_bfloat16* gp = (buf == 0) ? gAh : (buf == 1) ? gAl
                                    : (buf == 2) ? gBh : gBl;
            const void* src = gp + r * 128 + c * KC + cc * 8;
            asm volatile("cp.async.cg.shared.global [%0], [%1], 16;"
                :: "r"(dst), "l"(src));
        }
        asm volatile("cp.async.commit_group;");
    };

    // ---- chunk compute: k=32 (2 k16 steps), 3-term bf16 split ----
    // MMA stream is term-major over 8 accumulator quads (two j2 tiles jointly):
    // same-acc reuse distance = 8 -> HMMA accumulator RAW latency fully covered.
    auto compute_chunk = [&](uint32_t setbase) {
#pragma unroll
        for (int kk = 0; kk < 2; ++kk) {
            uint32_t ah0[4], al0[4], ah1[4], al1[4];
            const uint32_t ab = sbase + setbase + aoff + kk * 32;
            ldsm4(ah0, ab);
            ldsm4(ah1, ab + 16 * ROWB);
            ldsm4(al0, ab + BUFB);
            ldsm4(al1, ab + BUFB + 16 * ROWB);
#pragma unroll
            for (int j4 = 0; j4 < 2; ++j4) {
                uint32_t bha[4], bla[4], bhb[4], blb[4];
                const uint32_t bb = sbase + setbase + 2 * BUFB + boff
                                  + (2 * j4) * (16 * ROWB) + kk * 32;
                ldsm4(bha, bb);
                ldsm4(bla, bb + BUFB);
                ldsm4(bhb, bb + 16 * ROWB);
                ldsm4(blb, bb + BUFB + 16 * ROWB);
                float* c00a = acc + (4 * j4 + 0) * 4;        // n8 = 4j4+0
                float* c01a = acc + (4 * j4 + 1) * 4;        // n8 = 4j4+1
                float* c00b = acc + (4 * j4 + 2) * 4;        // n8 = 4j4+2
                float* c01b = acc + (4 * j4 + 3) * 4;        // n8 = 4j4+3
                float* c10a = acc + 32 + (4 * j4 + 0) * 4;
                float* c11a = acc + 32 + (4 * j4 + 1) * 4;
                float* c10b = acc + 32 + (4 * j4 + 2) * 4;
                float* c11b = acc + 32 + (4 * j4 + 3) * 4;
                // hh (distance-8 same-acc spacing from here on)
                mma16816(c00a, ah0, bha[0], bha[1]);
                mma16816(c01a, ah0, bha[2], bha[3]);
                mma16816(c10a, ah1, bha[0], bha[1]);
                mma16816(c11a, ah1, bha[2], bha[3]);
                mma16816(c00b, ah0, bhb[0], bhb[1]);
                mma16816(c01b, ah0, bhb[2], bhb[3]);
                mma16816(c10b, ah1, bhb[0], bhb[1]);
                mma16816(c11b, ah1, bhb[2], bhb[3]);
                // hl
                mma16816(c00a, ah0, bla[0], bla[1]);
                mma16816(c01a, ah0, bla[2], bla[3]);
                mma16816(c10a, ah1, bla[0], bla[1]);
                mma16816(c11a, ah1, bla[2], bla[3]);
                mma16816(c00b, ah0, blb[0], blb[1]);
                mma16816(c01b, ah0, blb[2], blb[3]);
                mma16816(c10b, ah1, blb[0], blb[1]);
                mma16816(c11b, ah1, blb[2], blb[3]);
                // lh
                mma16816(c00a, al0, bha[0], bha[1]);
                mma16816(c01a, al0, bha[2], bha[3]);
                mma16816(c10a, al1, bha[0], bha[1]);
                mma16816(c11a, al1, bha[2], bha[3]);
                mma16816(c00b, al0, bhb[0], bhb[1]);
                mma16816(c01b, al0, bhb[2], bhb[3]);
                mma16816(c10b, al1, bhb[0], bhb[1]);
                mma16816(c11b, al1, bhb[2], bhb[3]);
            }
        }
    };

    // ---- pipelined mainloop: 4 chunks, 2 buffer sets ----
    issue_chunk(0, 0);
    issue_chunk(1, SETB);
#pragma unroll
    for (int c = 0; c < 4; ++c) {
        if (c < 3) asm volatile("cp.async.wait_group 1;");
        else       asm volatile("cp.async.wait_group 0;");
        __syncthreads();                       // chunk c data visible to all
        compute_chunk((c & 1) ? SETB : 0);
        __syncthreads();                       // all reads of this set done
        if (c < 2) issue_chunk(c + 2, (c & 1) ? SETB : 0);
    }

    // ---- epilogue: acc-1 -> sM (fp32, stride 130) ----
    float* sM = reinterpret_cast<float*>(smem);
    {
        const int rr = lane >> 2;
        const int cb = (lane & 3) << 1;
#pragma unroll
        for (int mt = 0; mt < 2; ++mt) {
            const int r0 = 32 * mw + 16 * mt + rr;
#pragma unroll
            for (int n8 = 0; n8 < 8; ++n8) {
                const int col = 64 * nw + 8 * n8 + cb;
                float* c = acc + mt * 32 + n8 * 4;
                *reinterpret_cast<float2*>(&sM[r0 * SM_STRIDE + col])
                    = make_float2(c[0] - 1.0f, c[1] - 1.0f);
                *reinterpret_cast<float2*>(&sM[(r0 + 8) * SM_STRIDE + col])
                    = make_float2(c[2] - 1.0f, c[3] - 1.0f);
            }
        }
    }
    __syncthreads();

    // ---- PDE: single-warp register wavefront, no barriers ----
    // K[p][q] = K[p][q-1] + K[p-1][q] + K[p-1][q-1]*(M-1)[p-1][q-1], K[0][*]=K[*][0]=1
    // Lane r owns rows 4r+1..4r+4. shc(s) = neighbor cur3 pre-step = K[4r][s-1-4r];
    // shp(s) = K[4r][s-2-4r] = shc(s-1) -> carried register, ONE shfl per step.
    if (wid == 0) {
        const float* mp = sM + 516 * lane - 2;   // mp[129*i + s]
        const int p1 = 4 * lane + 1, p2 = p1 + 1, p3 = p1 + 2, p4 = p1 + 3;
        float cur0 = 1.f, cur1 = 1.f, cur2 = 1.f, cur3 = 1.f;
        float pr0 = 1.f, pr1 = 1.f, pr2 = 1.f;
        float shc_prev = 1.f;

        // phase A: s = 2..127 (guarded commits)
#pragma unroll 2
        for (int s = 2; s <= 127; ++s) {
            float shc = __shfl_up_sync(0xffffffffu, cur3, 1);
            if (lane == 0) shc = 1.f;
            const float shp = shc_prev;
            const float m0 = mp[s];
            const float m1 = mp[129 + s];
            const float m2 = mp[258 + s];
            const float m3 = mp[387 + s];
            const float v0 = cur0 + shc  + shp * m0;
            const float v1 = cur1 + cur0 + pr0 * m1;
            const float v2 = cur2 + cur1 + pr1 * m2;
            const float v3 = cur3 + cur2 + pr2 * m3;
            shc_prev = shc;
            if (s > p1) { pr0 = cur0; cur0 = v0; }
            if (s > p2) { pr1 = cur1; cur1 = v1; }
            if (s > p3) { pr2 = cur2; cur2 = v2; }
            if (s > p4) { cur3 = v3; }
        }
        // phase B: s = 128..254 (unguarded; post-completion garbage is harmless)
#pragma unroll 2
        for (int s = 128; s <= 254; ++s) {
            float shc = __shfl_up_sync(0xffffffffu, cur3, 1);
            if (lane == 0) shc = 1.f;
            const float shp = shc_prev;
            const float m0 = mp[s];
            const float m1 = mp[129 + s];
            const float m2 = mp[258 + s];
            const float m3 = mp[387 + s];
            const float v0 = cur0 + shc  + shp * m0;
            const float v1 = cur1 + cur0 + pr0 * m1;
            const float v2 = cur2 + cur1 + pr1 * m2;
            const float v3 = cur3 + cur2 + pr2 * m3;
            shc_prev = shc;
            pr0 = cur0; cur0 = v0;
            pr1 = cur1; cur1 = v1;
            pr2 = cur2; cur2 = v2;
            cur3 = v3;
        }
        // K[127][127] = row 127 (lane 31, i=2) update at s=254
        if (lane == 31) g_partials[bid] = w * cur2;
    }
    // warps 1..7 exit (only warp 0 reads sM now)
}

// ---------------- deterministic FP64 reduction ----------------
__global__ void sig_reduce_kernel(float* __restrict__ out) {
    __shared__ double sh[256];
    const int tid = threadIdx.x;
    double acc = 0.0;
    for (int i = tid; i < NP; i += 256) acc += (double)g_partials[i];
    sh[tid] = acc;
    __syncthreads();
    for (int s = 128; s > 0; s >>= 1) {
        if (tid < s) sh[tid] += sh[tid + s];
        __syncthreads();
    }
    if (tid == 0) out[0] = (float)(sh[0] * (1.0 / 4096.0));
}

extern "C" void kernel_launch(void* const* d_in, const int* in_sizes, int n_in,
                              void* d_out, int out_size) {
    const float* X = (const float*)d_in[0];
    const float* Y = (const float*)d_in[1];
    float* out = (float*)d_out;

    cudaFuncSetAttribute(sig_block_kernel,
                         cudaFuncAttributeMaxDynamicSharedMemorySize, SMEM_BYTES);

    sig_precompute_kernel<<<128, 256>>>(X, Y);
    sig_block_kernel<<<NP, 256, SMEM_BYTES>>>();
    sig_reduce_kernel<<<1, 256>>>(out);
}

// round 17
// speedup vs baseline: 1.2790x; 1.0511x over previous
#include <cuda_runtime.h>
#include <cuda_bf16.h>
#include <cstdint>

// ---------------- problem constants ----------------
#define AA 64
#define MSEQ 128
#define DD 128
#define MMI 127

#define NPAIR_TRI 2080
#define NP (2*NPAIR_TRI + AA*AA)          // 8256 pair-blocks

// ---------------- device scratch (no allocs) ----------------
// bf16 hi/lo increment tiles: [tsr(2)][seq(64)][row(128)][col(128)]
__device__ __align__(16) __nv_bfloat16 g_hi[2*64*128*128];   // 4 MB
__device__ __align__(16) __nv_bfloat16 g_lo[2*64*128*128];   // 4 MB
__device__ float g_partials[NP];

// ---------------- smem byte map (block kernel) ----------------
// GEMM phase: cp.async double-buffered K-chunks of 32.
// Per chunk-set: A_hi, A_lo, B_hi, B_lo buffers of 128 rows x 80B
// (64B data + 16B pad; ldsm row banks {0,20,8,28,16,4,24,12}*4: conflict-free).
#define KC 32
#define ROWB 80
#define BUFB 10240                        // 128*80
#define SETB 40960                        // 4 buffers per set
#define SMEM_BYTES 81920                  // 2 sets; occ 2 (163KB/SM)
// PDE phase aliases buffers: sM = (M-1) in per-lane-padded layout:
//   (M-1)[r][c] at float index 521*(r>>2) + 130*(r&3) + c + 2
// PDE lane l reads sM[517*l + 129*i + s]: lane stride 517 = 5 mod 32 -> conflict-free.
// Size: 31*521 + 3*130 + 127 + 2 + 1 = 16671 floats = 66684 B <= 81920.

__device__ __forceinline__ uint32_t smem_u32(const void* p) {
    uint32_t a;
    asm("{ .reg .u64 t; cvta.to.shared.u64 t, %1; cvt.u32.u64 %0, t; }" : "=r"(a) : "l"(p));
    return a;
}

__device__ __forceinline__ void ldsm4(uint32_t* r, uint32_t addr) {
    asm volatile("ldmatrix.sync.aligned.m8n8.x4.shared.b16 {%0,%1,%2,%3}, [%4];"
        : "=r"(r[0]), "=r"(r[1]), "=r"(r[2]), "=r"(r[3]) : "r"(addr));
}

__device__ __forceinline__ void mma16816(float* c, const uint32_t* a,
                                         uint32_t b0, uint32_t b1) {
    asm volatile(
        "mma.sync.aligned.m16n8k16.row.col.f32.bf16.bf16.f32 "
        "{%0,%1,%2,%3}, {%4,%5,%6,%7}, {%8,%9}, {%0,%1,%2,%3};"
        : "+f"(c[0]), "+f"(c[1]), "+f"(c[2]), "+f"(c[3])
        : "r"(a[0]), "r"(a[1]), "r"(a[2]), "r"(a[3]), "r"(b0), "r"(b1));
}

// ---------------- precompute: bf16 hi/lo increments ----------------
__global__ __launch_bounds__(256)
void sig_precompute_kernel(const float* __restrict__ X, const float* __restrict__ Y) {
    const int blk = blockIdx.x;                 // tsr*64 + seq
    const int seq = blk & 63;
    const int tsr = blk >> 6;
    const float* src = (tsr ? Y : X) + (size_t)seq * MSEQ * DD;
    __nv_bfloat16* hi = g_hi + (size_t)blk * 128 * 128;
    __nv_bfloat16* lo = g_lo + (size_t)blk * 128 * 128;

    const int tid = threadIdx.x;
#pragma unroll
    for (int i = 0; i < 16; ++i) {
        int idx = tid + i * 256;                // 0..4095 float4 groups
        int r  = idx >> 5;
        int c4 = (idx & 31) << 2;
        float4 cur = *reinterpret_cast<const float4*>(src + r * DD + c4);
        float4 nxt = (r < MMI) ? *reinterpret_cast<const float4*>(src + (r + 1) * DD + c4) : cur;
        float i0 = nxt.x - cur.x, i1 = nxt.y - cur.y, i2 = nxt.z - cur.z, i3 = nxt.w - cur.w;
        __nv_bfloat16 h0 = __float2bfloat16(i0), h1 = __float2bfloat16(i1);
        __nv_bfloat16 h2 = __float2bfloat16(i2), h3 = __float2bfloat16(i3);
        __nv_bfloat16 l0 = __float2bfloat16(i0 - __bfloat162float(h0));
        __nv_bfloat16 l1 = __float2bfloat16(i1 - __bfloat162float(h1));
        __nv_bfloat16 l2 = __float2bfloat16(i2 - __bfloat162float(h2));
        __nv_bfloat16 l3 = __float2bfloat16(i3 - __bfloat162float(h3));
        __nv_bfloat162 hp0(h0, h1), hp1(h2, h3), lp0(l0, l1), lp1(l2, l3);
        uint2 hv, lv;
        hv.x = *reinterpret_cast<uint32_t*>(&hp0); hv.y = *reinterpret_cast<uint32_t*>(&hp1);
        lv.x = *reinterpret_cast<uint32_t*>(&lp0); lv.y = *reinterpret_cast<uint32_t*>(&lp1);
        *reinterpret_cast<uint2*>(hi + r * 128 + c4) = hv;
        *reinterpret_cast<uint2*>(lo + r * 128 + c4) = lv;
    }
}

// ---------------- fused per-pair kernel ----------------
__global__ __launch_bounds__(256, 2)
void sig_block_kernel() {
    extern __shared__ unsigned char smem[];
    const uint32_t sbase = smem_u32(smem);
    const int bid = blockIdx.x;
    const int tid = threadIdx.x;
    const int wid = tid >> 5, lane = tid & 31;

    // ---- decode (gram type, pair) ----
    int g, a, b;
    float w;
    if (bid < 2 * NPAIR_TRI) {
        g = (bid < NPAIR_TRI) ? 0 : 1;
        int t = bid - g * NPAIR_TRI;
        int aa = 0;
        while (t >= (AA - aa)) { t -= (AA - aa); ++aa; }
        a = aa; b = aa + t;
        w = (a == b) ? 1.0f : 2.0f;
    } else {
        g = 2;
        int t = bid - 2 * NPAIR_TRI;
        a = t >> 6; b = t & 63;
        w = -2.0f;
    }
    const int idxA = ((g == 1) ? 64 : 0) + a;     // Y for YY else X
    const int idxB = ((g == 0) ? 0 : 64) + b;     // X for XX else Y
    const __nv_bfloat16* gAh = g_hi + (size_t)idxA * 16384;
    const __nv_bfloat16* gAl = g_lo + (size_t)idxA * 16384;
    const __nv_bfloat16* gBh = g_hi + (size_t)idxB * 16384;
    const __nv_bfloat16* gBl = g_lo + (size_t)idxB * 16384;

    // ---- warp tile: m32 x n64 (4 x 2 warp grid) ----
    const int mw = wid >> 1, nw = wid & 1;
    const int ablk = lane >> 3;
    const int arow = ((ablk & 1) << 3) + (lane & 7);
    const uint32_t aoff = (uint32_t)((32 * mw + arow) * ROWB + ((ablk >> 1) << 4));
    const int bblk = lane >> 3;
    const uint32_t boff = (uint32_t)((64 * nw + ((bblk >> 1) << 3) + (lane & 7)) * ROWB
                                     + ((bblk & 1) << 4));

    float acc[64];
#pragma unroll
    for (int i = 0; i < 64; ++i) acc[i] = 0.0f;

    // ---- cp.async chunk loader: 8 x 16B per thread per chunk ----
    auto issue_chunk = [&](int c, uint32_t setbase) {
#pragma unroll
        for (int j = 0; j < 8; ++j) {
            int idx = tid + j * 256;            // 0..2047
            int buf = idx >> 9;                 // 0..3
            int r   = (idx >> 2) & 127;
            int cc  = idx & 3;                  // 16B column within 64B row data
            uint32_t dst = sbase + setbase + buf * BUFB + (uint32_t)(r * ROWB + cc * 16);
            const __nv_bfloat16* gp = (buf == 0) ? gAh : (buf == 1) ? gAl
                                    : (buf == 2) ? gBh : gBl;
            const void* src = gp + r * 128 + c * KC + cc * 8;
            asm volatile("cp.async.cg.shared.global [%0], [%1], 16;"
                :: "r"(dst), "l"(src));
        }
        asm volatile("cp.async.commit_group;");
    };

    // ---- chunk compute: k=32 (2 k16 steps), 3-term bf16 split ----
    auto compute_chunk = [&](uint32_t setbase) {
#pragma unroll
        for (int kk = 0; kk < 2; ++kk) {
            uint32_t ah0[4], al0[4], ah1[4], al1[4];
            const uint32_t ab = sbase + setbase + aoff + kk * 32;
            ldsm4(ah0, ab);
            ldsm4(ah1, ab + 16 * ROWB);
            ldsm4(al0, ab + BUFB);
            ldsm4(al1, ab + BUFB + 16 * ROWB);
#pragma unroll
            for (int j4 = 0; j4 < 2; ++j4) {
                uint32_t bha[4], bla[4], bhb[4], blb[4];
                const uint32_t bb = sbase + setbase + 2 * BUFB + boff
                                  + (2 * j4) * (16 * ROWB) + kk * 32;
                ldsm4(bha, bb);
                ldsm4(bla, bb + BUFB);
                ldsm4(bhb, bb + 16 * ROWB);
                ldsm4(blb, bb + BUFB + 16 * ROWB);
                float* c00a = acc + (4 * j4 + 0) * 4;
                float* c01a = acc + (4 * j4 + 1) * 4;
                float* c00b = acc + (4 * j4 + 2) * 4;
                float* c01b = acc + (4 * j4 + 3) * 4;
                float* c10a = acc + 32 + (4 * j4 + 0) * 4;
                float* c11a = acc + 32 + (4 * j4 + 1) * 4;
                float* c10b = acc + 32 + (4 * j4 + 2) * 4;
                float* c11b = acc + 32 + (4 * j4 + 3) * 4;
                mma16816(c00a, ah0, bha[0], bha[1]);
                mma16816(c01a, ah0, bha[2], bha[3]);
                mma16816(c10a, ah1, bha[0], bha[1]);
                mma16816(c11a, ah1, bha[2], bha[3]);
                mma16816(c00b, ah0, bhb[0], bhb[1]);
                mma16816(c01b, ah0, bhb[2], bhb[3]);
                mma16816(c10b, ah1, bhb[0], bhb[1]);
                mma16816(c11b, ah1, bhb[2], bhb[3]);
                mma16816(c00a, ah0, bla[0], bla[1]);
                mma16816(c01a, ah0, bla[2], bla[3]);
                mma16816(c10a, ah1, bla[0], bla[1]);
                mma16816(c11a, ah1, bla[2], bla[3]);
                mma16816(c00b, ah0, blb[0], blb[1]);
                mma16816(c01b, ah0, blb[2], blb[3]);
                mma16816(c10b, ah1, blb[0], blb[1]);
                mma16816(c11b, ah1, blb[2], blb[3]);
                mma16816(c00a, al0, bha[0], bha[1]);
                mma16816(c01a, al0, bha[2], bha[3]);
                mma16816(c10a, al1, bha[0], bha[1]);
                mma16816(c11a, al1, bha[2], bha[3]);
                mma16816(c00b, al0, bhb[0], bhb[1]);
                mma16816(c01b, al0, bhb[2], bhb[3]);
                mma16816(c10b, al1, bhb[0], bhb[1]);
                mma16816(c11b, al1, bhb[2], bhb[3]);
            }
        }
    };

    // ---- pipelined mainloop: 4 chunks, 2 buffer sets ----
    issue_chunk(0, 0);
    issue_chunk(1, SETB);
#pragma unroll
    for (int c = 0; c < 4; ++c) {
        if (c < 3) asm volatile("cp.async.wait_group 1;");
        else       asm volatile("cp.async.wait_group 0;");
        __syncthreads();                       // chunk c data visible to all
        compute_chunk((c & 1) ? SETB : 0);
        __syncthreads();                       // all reads of this set done
        if (c < 2) issue_chunk(c + 2, (c & 1) ? SETB : 0);
    }

    // ---- epilogue: acc-1 -> sM in per-lane-padded PDE layout ----
    // (M-1)[r][c] at float index 521*(r>>2) + 130*(r&3) + c + 2
    float* sM = reinterpret_cast<float*>(smem);
    {
        const int rr = lane >> 2;
        const int cb = (lane & 3) << 1;
#pragma unroll
        for (int mt = 0; mt < 2; ++mt) {
            const int rA = 32 * mw + 16 * mt + rr;
            const int rB = rA + 8;
            const int baseA = 521 * (rA >> 2) + 130 * (rA & 3) + 2;
            const int baseB = 521 * (rB >> 2) + 130 * (rB & 3) + 2;
#pragma unroll
            for (int n8 = 0; n8 < 8; ++n8) {
                const int col = 64 * nw + 8 * n8 + cb;
                float* c = acc + mt * 32 + n8 * 4;
                sM[baseA + col]     = c[0] - 1.0f;
                sM[baseA + col + 1] = c[1] - 1.0f;
                sM[baseB + col]     = c[2] - 1.0f;
                sM[baseB + col + 1] = c[3] - 1.0f;
            }
        }
    }
    __syncthreads();

    // ---- PDE: single-warp register wavefront, no barriers ----
    // K[p][q] = K[p][q-1] + K[p-1][q] + K[p-1][q-1]*(M-1)[p-1][q-1], K[0][*]=K[*][0]=1
    // Lane l owns rows 4l+1..4l+4. shc(s) = neighbor cur3 pre-step = K[4l][s-1-4l];
    // shp(s) = shc(s-1) carried in a register -> ONE shfl per step.
    // m_i read at sM[517*l + 129*i + s]: lane stride 517 (5 mod 32) -> conflict-free.
    if (wid == 0) {
        const float* mp = sM + 517 * lane;       // mp[129*i + s]
        const int p1 = 4 * lane + 1, p2 = p1 + 1, p3 = p1 + 2, p4 = p1 + 3;
        float cur0 = 1.f, cur1 = 1.f, cur2 = 1.f, cur3 = 1.f;
        float pr0 = 1.f, pr1 = 1.f, pr2 = 1.f;
        float shc_prev = 1.f;

        // phase A: s = 2..127 (guarded commits)
#pragma unroll 2
        for (int s = 2; s <= 127; ++s) {
            float shc = __shfl_up_sync(0xffffffffu, cur3, 1);
            if (lane == 0) shc = 1.f;
            const float shp = shc_prev;
            const float m0 = mp[s];
            const float m1 = mp[129 + s];
            const float m2 = mp[258 + s];
            const float m3 = mp[387 + s];
            const float v0 = cur0 + shc  + shp * m0;
            const float v1 = cur1 + cur0 + pr0 * m1;
            const float v2 = cur2 + cur1 + pr1 * m2;
            const float v3 = cur3 + cur2 + pr2 * m3;
            shc_prev = shc;
            if (s > p1) { pr0 = cur0; cur0 = v0; }
            if (s > p2) { pr1 = cur1; cur1 = v1; }
            if (s > p3) { pr2 = cur2; cur2 = v2; }
            if (s > p4) { cur3 = v3; }
        }
        // phase B: s = 128..254 (unguarded; post-completion garbage is harmless)
#pragma unroll 2
        for (int s = 128; s <= 254; ++s) {
            float shc = __shfl_up_sync(0xffffffffu, cur3, 1);
            if (lane == 0) shc = 1.f;
            const float shp = shc_prev;
            const float m0 = mp[s];
            const float m1 = mp[129 + s];
            const float m2 = mp[258 + s];
            const float m3 = mp[387 + s];
            const float v0 = cur0 + shc  + shp * m0;
            const float v1 = cur1 + cur0 + pr0 * m1;
            const float v2 = cur2 + cur1 + pr1 * m2;
            const float v3 = cur3 + cur2 + pr2 * m3;
            shc_prev = shc;
            pr0 = cur0; cur0 = v0;
            pr1 = cur1; cur1 = v1;
            pr2 = cur2; cur2 = v2;
            cur3 = v3;
        }
        // K[127][127] = row 127 (lane 31, i=2) update at s=254
        if (lane == 31) g_partials[bid] = w * cur2;
    }
    // warps 1..7 exit (only warp 0 reads sM now)
}

// ---------------- deterministic FP64 reduction ----------------
__global__ void sig_reduce_kernel(float* __restrict__ out) {
    __shared__ double sh[256];
    const int tid = threadIdx.x;
    double acc = 0.0;
    for (int i = tid; i < NP; i += 256) acc += (double)g_partials[i];
    sh[tid] = acc;
    __syncthreads();
    for (int s = 128; s > 0; s >>= 1) {
        if (tid < s) sh[tid] += sh[tid + s];
        __syncthreads();
    }
    if (tid == 0) out[0] = (float)(sh[0] * (1.0 / 4096.0));
}

extern "C" void kernel_launch(void* const* d_in, const int* in_sizes, int n_in,
                              void* d_out, int out_size) {
    const float* X = (const float*)d_in[0];
    const float* Y = (const float*)d_in[1];
    float* out = (float*)d_out;

    cudaFuncSetAttribute(sig_block_kernel,
                         cudaFuncAttributeMaxDynamicSharedMemorySize, SMEM_BYTES);

    sig_precompute_kernel<<<128, 256>>>(X, Y);
    sig_block_kernel<<<NP, 256, SMEM_BYTES>>>();
    sig_reduce_kernel<<<1, 256>>>(out);
}